// round 17
// baseline (speedup 1.0000x reference)
#include <cuda_runtime.h>
#include <cuda_bf16.h>
#include <math.h>
#include <stddef.h>
#include <stdint.h>

// Problem constants
#define B_  2
#define S_  2048
#define D_  1024
#define H_  16
#define FK_ 32
#define DK_ 64
#define BH_ (B_*H_)
#define M_ROWS (B_*S_)      // 4096

// ---------------- scratch (__device__ globals; no allocation allowed) ----------------
__device__ float g_L [H_*DK_*FK_];
__device__ float g_RT[H_*DK_*FK_];
__device__ float g_vp[B_*S_*D_];
__device__ float g_concat[B_*S_*D_];
__device__ float g_X[BH_*S_*FK_];
__device__ float g_Y[BH_*S_*FK_];
__device__ __nv_bfloat16 g_Xh[BH_*S_*FK_], g_Xl[BH_*S_*FK_];
__device__ __nv_bfloat16 g_Yh[BH_*S_*FK_], g_Yl[BH_*S_*FK_];
__device__ __nv_bfloat16 g_WvhT[D_*D_], g_WvlT[D_*D_];
__device__ __nv_bfloat16 g_WohT[D_*D_], g_WolT[D_*D_];

// ---------------- HMMA helpers ----------------
__device__ __forceinline__ uint32_t smem_u32(const void* p) {
    uint32_t a;
    asm("{ .reg .u64 t; cvta.to.shared.u64 t, %1; cvt.u32.u64 %0, t; }" : "=r"(a) : "l"(p));
    return a;
}
__device__ __forceinline__ void ldmx4(uint32_t* r, uint32_t addr) {
    asm volatile("ldmatrix.sync.aligned.m8n8.x4.shared.b16 {%0,%1,%2,%3}, [%4];"
                 : "=r"(r[0]), "=r"(r[1]), "=r"(r[2]), "=r"(r[3]) : "r"(addr));
}
__device__ __forceinline__ void ldmx2(uint32_t* r, uint32_t addr) {
    asm volatile("ldmatrix.sync.aligned.m8n8.x2.shared.b16 {%0,%1}, [%2];"
                 : "=r"(r[0]), "=r"(r[1]) : "r"(addr));
}
__device__ __forceinline__ void mma_bf16(float* c, const uint32_t* a, const uint32_t* b) {
    asm volatile(
        "mma.sync.aligned.m16n8k16.row.col.f32.bf16.bf16.f32 "
        "{%0,%1,%2,%3}, {%4,%5,%6,%7}, {%8,%9}, {%0,%1,%2,%3};"
        : "+f"(c[0]), "+f"(c[1]), "+f"(c[2]), "+f"(c[3])
        : "r"(a[0]), "r"(a[1]), "r"(a[2]), "r"(a[3]), "r"(b[0]), "r"(b[1]));
}
__device__ __forceinline__ uint32_t swoff(int row, int chunk) {
    return (uint32_t)(row * 128 + ((chunk ^ (row & 7)) * 16));
}
__device__ __forceinline__ uint32_t pack_hi2(float a, float b) {
    __nv_bfloat162 t = __floats2bfloat162_rn(a, b);
    return *(uint32_t*)&t;
}

// ---------------- 1) collapse Wa@Wb@Wa2 per head (fp32) + RT transpose ----------
__global__ void compute_L_kernel(const float* __restrict__ W_A,
                                 const float* __restrict__ W_A2) {
    int h = blockIdx.x;
    __shared__ float T1[64*64];
    const float* WAh  = W_A  + h*2048;
    const float* WA2h = W_A2 + h*2048;

    for (int idx = threadIdx.x; idx < 4096; idx += blockDim.x) {
        int c = idx >> 6, d = idx & 63;
        float acc = 0.f;
        #pragma unroll 8
        for (int j = 0; j < 32; j++)
            acc = fmaf(WAh[c*32 + j], WAh[j*64 + d], acc);
        T1[idx] = acc;
    }
    __syncthreads();
    for (int idx = threadIdx.x; idx < 2048; idx += blockDim.x) {
        int c = idx >> 5, j = idx & 31;
        float acc = 0.f;
        #pragma unroll 8
        for (int d = 0; d < 64; d++)
            acc = fmaf(T1[c*64 + d], WA2h[d*32 + j], acc);
        g_L[h*2048 + c*32 + j] = acc;
    }
    for (int idx = threadIdx.x; idx < 2048; idx += blockDim.x) {
        int d = idx >> 5, j = idx & 31;
        g_RT[h*2048 + d*32 + j] = WA2h[j*64 + d];
    }
}

// ---------------- 2) X,Y (fp32 + bf16 hi/lo splits) per head ----------
__global__ __launch_bounds__(512)
void xy_kernel(const float* __restrict__ q) {
    int token = blockIdx.x;
    int b = token >> 11, s = token & 2047;
    __shared__ float qs[D_];
    const float* qrow = q + (size_t)token * D_;
    for (int i = threadIdx.x; i < D_; i += 512) qs[i] = qrow[i];
    __syncthreads();
    int j = threadIdx.x & 31;
    int h = threadIdx.x >> 5;
    const float* qh = qs + h*64;
    const float* Lh  = g_L  + h*2048 + j;
    const float* RTh = g_RT + h*2048 + j;
    float x = 0.f, y = 0.f;
    #pragma unroll 8
    for (int c = 0; c < 64; c++) x = fmaf(qh[c], Lh[c*32], x);
    #pragma unroll 8
    for (int d = 0; d < 64; d++) y = fmaf(qh[d], RTh[d*32], y);
    size_t o = (((size_t)(b*16 + h))*2048 + s)*32 + j;
    g_X[o] = x;
    g_Y[o] = y;
    __nv_bfloat16 xh = __float2bfloat16(x);
    g_Xh[o] = xh;
    g_Xl[o] = __float2bfloat16(x - __bfloat162float(xh));
    __nv_bfloat16 yh = __float2bfloat16(y);
    g_Yh[o] = yh;
    g_Yl[o] = __float2bfloat16(y - __bfloat162float(yh));
}

// ---------------- 2c) split + transpose weights ----------
__global__ __launch_bounds__(256)
void split_wt_kernel(const float* __restrict__ W,
                     __nv_bfloat16* __restrict__ hiT,
                     __nv_bfloat16* __restrict__ loT) {
    __shared__ float t[32][33];
    int n0 = blockIdx.x * 32, k0 = blockIdx.y * 32;
    int x = threadIdx.x & 31, y = threadIdx.x >> 5;
    #pragma unroll
    for (int i = y; i < 32; i += 8)
        t[i][x] = W[(size_t)(k0 + i) * D_ + n0 + x];
    __syncthreads();
    #pragma unroll
    for (int i = y; i < 32; i += 8) {
        float v = t[x][i];
        __nv_bfloat16 vh = __float2bfloat16(v);
        size_t o = (size_t)(n0 + i) * D_ + k0 + x;
        hiT[o] = vh;
        loT[o] = __float2bfloat16(v - __bfloat162float(vh));
    }
}

// ---------------- 3) split-bf16 HMMA SGEMM (inline activation split) ----------
#define HS_A  0
#define HS_AL 16384
#define HS_W  32768
#define HS_WL 49152
#define SMEM_HMMA 65536

__global__ __launch_bounds__(256, 2)
void hmma_sgemm(const float* __restrict__ A,
                const __nv_bfloat16* __restrict__ WTh,
                const __nv_bfloat16* __restrict__ WTl,
                const float* __restrict__ bias,
                float* __restrict__ C) {
    extern __shared__ __align__(128) char sm[];
    uint32_t smb = smem_u32(sm);

    int tid = threadIdx.x, lane = tid & 31, wid = tid >> 5;
    int bn = blockIdx.x * 128;
    int bm = blockIdx.y * 128;
    int warp_m = wid >> 1;
    int warp_n = wid & 1;
    int mrow0 = warp_m * 32;
    int nrow0 = warp_n * 64;

    float acc[2][8][4];
    #pragma unroll
    for (int mf = 0; mf < 2; mf++)
        #pragma unroll
        for (int nf = 0; nf < 8; nf++)
            #pragma unroll
            for (int c = 0; c < 4; c++) acc[mf][nf][c] = 0.f;

    int srow = tid >> 1;
    int shalf = tid & 1;

    for (int kt = 0; kt < 16; kt++) {
        int k0 = kt * 64;
        {
            const float4* pA = (const float4*)(A + (size_t)(bm + srow)*D_ + k0);
            const uint4*  pWh = (const uint4*)(WTh + (size_t)(bn + srow)*D_ + k0);
            const uint4*  pWl = (const uint4*)(WTl + (size_t)(bn + srow)*D_ + k0);
            #pragma unroll
            for (int cc = 0; cc < 4; cc++) {
                int chunk = shalf*4 + cc;
                float4 f0 = pA[chunk*2];
                float4 f1 = pA[chunk*2 + 1];
                __nv_bfloat16 h0 = __float2bfloat16(f0.x), h1 = __float2bfloat16(f0.y);
                __nv_bfloat16 h2 = __float2bfloat16(f0.z), h3 = __float2bfloat16(f0.w);
                __nv_bfloat16 h4 = __float2bfloat16(f1.x), h5 = __float2bfloat16(f1.y);
                __nv_bfloat16 h6 = __float2bfloat16(f1.z), h7 = __float2bfloat16(f1.w);
                uint4 hv, lv;
                hv.x = pack_hi2(f0.x, f0.y); hv.y = pack_hi2(f0.z, f0.w);
                hv.z = pack_hi2(f1.x, f1.y); hv.w = pack_hi2(f1.z, f1.w);
                lv.x = pack_hi2(f0.x - __bfloat162float(h0), f0.y - __bfloat162float(h1));
                lv.y = pack_hi2(f0.z - __bfloat162float(h2), f0.w - __bfloat162float(h3));
                lv.z = pack_hi2(f1.x - __bfloat162float(h4), f1.y - __bfloat162float(h5));
                lv.w = pack_hi2(f1.z - __bfloat162float(h6), f1.w - __bfloat162float(h7));
                uint32_t o = swoff(srow, chunk);
                *(uint4*)(sm + HS_A  + o) = hv;
                *(uint4*)(sm + HS_AL + o) = lv;
                *(uint4*)(sm + HS_W  + o) = pWh[chunk];
                *(uint4*)(sm + HS_WL + o) = pWl[chunk];
            }
        }
        __syncthreads();

        #pragma unroll
        for (int ks = 0; ks < 4; ks++) {
            uint32_t ah[2][4], al[2][4];
            #pragma unroll
            for (int mf = 0; mf < 2; mf++) {
                int row = mrow0 + mf*16 + (lane & 7) + ((lane >> 3) & 1) * 8;
                int chunk = 2*ks + (lane >> 4);
                uint32_t o = swoff(row, chunk);
                ldmx4(ah[mf], smb + HS_A  + o);
                ldmx4(al[mf], smb + HS_AL + o);
            }
            #pragma unroll
            for (int nf = 0; nf < 8; nf++) {
                int row = nrow0 + nf*8 + (lane & 7);
                int chunk = 2*ks + ((lane >> 3) & 1);
                uint32_t o = swoff(row, chunk);
                uint32_t bh[2], bl[2];
                ldmx2(bh, smb + HS_W  + o);
                ldmx2(bl, smb + HS_WL + o);
                #pragma unroll
                for (int mf = 0; mf < 2; mf++) {
                    mma_bf16(acc[mf][nf], ah[mf], bh);
                    mma_bf16(acc[mf][nf], ah[mf], bl);
                    mma_bf16(acc[mf][nf], al[mf], bh);
                }
            }
        }
        __syncthreads();
    }

    #pragma unroll
    for (int mf = 0; mf < 2; mf++) {
        int r0 = bm + mrow0 + mf*16 + (lane >> 2);
        #pragma unroll
        for (int nf = 0; nf < 8; nf++) {
            int cc = bn + nrow0 + nf*8 + 2*(lane & 3);
            float2 b01 = make_float2(bias[cc], bias[cc+1]);
            *(float2*)&C[(size_t)r0*D_ + cc] =
                make_float2(acc[mf][nf][0] + b01.x, acc[mf][nf][1] + b01.y);
            *(float2*)&C[(size_t)(r0+8)*D_ + cc] =
                make_float2(acc[mf][nf][2] + b01.x, acc[mf][nf][3] + b01.y);
        }
    }
}

// ---------------- 4) FUSED: HMMA approx scores + exact rescore + online softmax ----
// Approx scores (split-bf16, err |d|<~20) drive skip/capture only (margin 140 =
// 95 + 2*22). Captured elements are exactly rescored with the fp32 dot X.Y in
// k-ascending fmaf order (identical values + order as R14's fp32 GEMM), then the
// SAME dx>-95 cut and online update -> output bit-identical to R14/R16 fused.
#define SCS 132
#define SM_A    0          // bf16 A tile [128][chunks: 0-3 hi | 4-7 lo]
#define SM_B    16384
#define SM_SC   32768
#define SM_RMX0 (SM_SC + 128*SCS*4)
#define SM_RMX1 (SM_RMX0 + 512)
#define SMEM_FUSED (SM_RMX1 + 512)

__global__ __launch_bounds__(256, 2)
void fused_attn_kernel() {
    extern __shared__ __align__(128) char sm[];
    uint32_t smb = smem_u32(sm);
    float* SC   = (float*)(sm + SM_SC);
    float* RMX0 = (float*)(sm + SM_RMX0);
    float* RMX1 = (float*)(sm + SM_RMX1);

    int tid = threadIdx.x, lane = tid & 31, wid = tid >> 5;
    int stile = blockIdx.x, bh = blockIdx.y;
    int b = bh >> 4, h = bh & 15;
    int s0 = stile * 128;
    int warp_m = wid >> 1, warp_n = wid & 1;
    int mrow0 = warp_m * 32, nrow0 = warp_n * 64;

    const float NEG_INF = __int_as_float(0xff800000);

    int srow = tid & 127, shalf = tid >> 7;

    // ---- stage A tile once: Xh chunks 0-3, Xl chunks 4-7 ----
    {
        const uint4* ph = (const uint4*)(g_Xh + ((size_t)bh*2048 + s0 + srow)*32);
        const uint4* pl = (const uint4*)(g_Xl + ((size_t)bh*2048 + s0 + srow)*32);
        #pragma unroll
        for (int c = 0; c < 2; c++) {
            int ch = 2*shalf + c;
            *(uint4*)(sm + SM_A + swoff(srow, ch))     = ph[ch];
            *(uint4*)(sm + SM_A + swoff(srow, 4 + ch)) = pl[ch];
        }
    }

    // ---- scan/PV state ----
    int rt = tid >> 1, half = tid & 1;
    int rowg = bh*2048 + s0 + rt;
    const float4* xrow = (const float4*)(g_X + (size_t)rowg * 32);
    const float*  Yf   = g_Y + (size_t)bh*2048*32;
    const float* vbase = g_vp + (size_t)b*2048*D_ + h*64 + half*32;
    float m  = NEG_INF;    // exact running max
    float mt = NEG_INF;    // approx running max (selection only)
    float den = 0.f;
    float4 o4[8];
    #pragma unroll
    for (int jj = 0; jj < 8; jj++) o4[jj] = make_float4(0.f, 0.f, 0.f, 0.f);

    for (int tt = 0; tt < 16; tt++) {
        int t0 = tt * 128;
        // ---- stage B tile: Yh chunks 0-3, Yl chunks 4-7 ----
        {
            const uint4* ph = (const uint4*)(g_Yh + ((size_t)bh*2048 + t0 + srow)*32);
            const uint4* pl = (const uint4*)(g_Yl + ((size_t)bh*2048 + t0 + srow)*32);
            #pragma unroll
            for (int c = 0; c < 2; c++) {
                int ch = 2*shalf + c;
                *(uint4*)(sm + SM_B + swoff(srow, ch))     = ph[ch];
                *(uint4*)(sm + SM_B + swoff(srow, 4 + ch)) = pl[ch];
            }
        }
        __syncthreads();

        // ---- 128x128 approx scores via 3-product split-bf16 HMMA ----
        float acc[2][8][4];
        #pragma unroll
        for (int mf = 0; mf < 2; mf++)
            #pragma unroll
            for (int nf = 0; nf < 8; nf++)
                #pragma unroll
                for (int c = 0; c < 4; c++) acc[mf][nf][c] = 0.f;

        #pragma unroll
        for (int ks = 0; ks < 2; ks++) {
            uint32_t ahf[2][4], alf[2][4];
            #pragma unroll
            for (int mf = 0; mf < 2; mf++) {
                int row = mrow0 + mf*16 + (lane & 7) + ((lane >> 3) & 1) * 8;
                int ch = 2*ks + (lane >> 4);
                ldmx4(ahf[mf], smb + SM_A + swoff(row, ch));
                ldmx4(alf[mf], smb + SM_A + swoff(row, 4 + ch));
            }
            #pragma unroll
            for (int nf = 0; nf < 8; nf++) {
                int row = nrow0 + nf*8 + (lane & 7);
                int ch = 2*ks + ((lane >> 3) & 1);
                uint32_t bhf[2], blf[2];
                ldmx2(bhf, smb + SM_B + swoff(row, ch));
                ldmx2(blf, smb + SM_B + swoff(row, 4 + ch));
                #pragma unroll
                for (int mf = 0; mf < 2; mf++) {
                    mma_bf16(acc[mf][nf], ahf[mf], bhf);
                    mma_bf16(acc[mf][nf], ahf[mf], blf);
                    mma_bf16(acc[mf][nf], alf[mf], bhf);
                }
            }
        }

        // ---- per-row tile max (per n-half) + unconditional spill ----
        #pragma unroll
        for (int mf = 0; mf < 2; mf++) {
            int r0 = mrow0 + mf*16 + (lane >> 2);
            float rm0 = NEG_INF, rm1 = NEG_INF;
            #pragma unroll
            for (int nf = 0; nf < 8; nf++) {
                rm0 = fmaxf(rm0, fmaxf(acc[mf][nf][0], acc[mf][nf][1]));
                rm1 = fmaxf(rm1, fmaxf(acc[mf][nf][2], acc[mf][nf][3]));
            }
            rm0 = fmaxf(rm0, __shfl_xor_sync(0xFFFFFFFFu, rm0, 1));
            rm0 = fmaxf(rm0, __shfl_xor_sync(0xFFFFFFFFu, rm0, 2));
            rm1 = fmaxf(rm1, __shfl_xor_sync(0xFFFFFFFFu, rm1, 1));
            rm1 = fmaxf(rm1, __shfl_xor_sync(0xFFFFFFFFu, rm1, 2));
            if ((lane & 3) == 0) {
                if (warp_n == 0) { RMX0[r0] = rm0; RMX0[r0+8] = rm1; }
                else             { RMX1[r0] = rm0; RMX1[r0+8] = rm1; }
            }
            #pragma unroll
            for (int nf = 0; nf < 8; nf++) {
                int cc = nrow0 + nf*8 + 2*(lane & 3);
                *(float2*)&SC[r0*SCS + cc]     = make_float2(acc[mf][nf][0], acc[mf][nf][1]);
                *(float2*)&SC[(r0+8)*SCS + cc] = make_float2(acc[mf][nf][2], acc[mf][nf][3]);
            }
        }
        __syncthreads();

        // ---- scan: approx skip (margin 140), exact rescore + online update ----
        float rowmax = fmaxf(RMX0[rt], RMX1[rt]);
        if (rowmax > mt - 140.0f) {
            const float* rp = SC + rt*SCS;
            #pragma unroll 4
            for (int j4 = 0; j4 < 32; j4++) {
                float4 x4 = *(const float4*)(rp + j4*4);
                float mx4 = fmaxf(fmaxf(x4.x, x4.y), fmaxf(x4.z, x4.w));
                if (mx4 <= mt - 140.0f) continue;
                float xs[4] = {x4.x, x4.y, x4.z, x4.w};
                #pragma unroll
                for (int u = 0; u < 4; u++) {
                    float xa = xs[u];
                    if (xa > mt - 140.0f) {
                        int t = t0 + j4*4 + u;
                        // exact fp32 rescore: same values + summation order as R14
                        const float4* yp = (const float4*)(Yf + (size_t)t * 32);
                        float ex = 0.f;
                        #pragma unroll
                        for (int i2 = 0; i2 < 8; i2++) {
                            float4 a = xrow[i2], bb = yp[i2];
                            ex = fmaf(a.x, bb.x, ex);
                            ex = fmaf(a.y, bb.y, ex);
                            ex = fmaf(a.z, bb.z, ex);
                            ex = fmaf(a.w, bb.w, ex);
                        }
                        if (ex > m) {
                            float r = __expf(m - ex);
                            den = den * r + 1.f;
                            const float4* vr = (const float4*)(vbase + (size_t)t * D_);
                            #pragma unroll
                            for (int jj = 0; jj < 8; jj++) {
                                float4 v = vr[jj];
                                o4[jj].x = fmaf(o4[jj].x, r, v.x);
                                o4[jj].y = fmaf(o4[jj].y, r, v.y);
                                o4[jj].z = fmaf(o4[jj].z, r, v.z);
                                o4[jj].w = fmaf(o4[jj].w, r, v.w);
                            }
                            m = ex;
                        } else {
                            float dx = ex - m;
                            if (dx > -95.0f) {
                                float w = __expf(dx);
                                den += w;
                                const float4* vr = (const float4*)(vbase + (size_t)t * D_);
                                #pragma unroll
                                for (int jj = 0; jj < 8; jj++) {
                                    float4 v = vr[jj];
                                    o4[jj].x = fmaf(w, v.x, o4[jj].x);
                                    o4[jj].y = fmaf(w, v.y, o4[jj].y);
                                    o4[jj].z = fmaf(w, v.z, o4[jj].z);
                                    o4[jj].w = fmaf(w, v.w, o4[jj].w);
                                }
                            }
                        }
                    }
                    if (xa > mt) mt = xa;
                }
            }
        }
        __syncthreads();
    }

    float inv = 1.f / den;
    float* op = g_concat + ((size_t)(b*2048 + s0 + rt))*D_ + h*64 + half*32;
    #pragma unroll
    for (int jj = 0; jj < 8; jj++) {
        float4 r = o4[jj];
        r.x *= inv; r.y *= inv; r.z *= inv; r.w *= inv;
        *(float4*)(op + jj*4) = r;
    }
}

// ---------------- launcher ----------------
extern "C" void kernel_launch(void* const* d_in, const int* in_sizes, int n_in,
                              void* d_out, int out_size) {
    const float* q    = (const float*)d_in[0];
    // d_in[1] = k (unused in reference forward)
    const float* v    = (const float*)d_in[2];
    const float* Wv   = (const float*)d_in[3];
    const float* bv   = (const float*)d_in[4];
    const float* W_A  = (const float*)d_in[5];
    const float* W_A2 = (const float*)d_in[6];
    const float* Wo   = (const float*)d_in[7];
    const float* bo   = (const float*)d_in[8];
    float* out = (float*)d_out;

    float* vp;     cudaGetSymbolAddress((void**)&vp,     g_vp);
    float* concat; cudaGetSymbolAddress((void**)&concat, g_concat);
    __nv_bfloat16 *WvhT, *WvlT, *WohT, *WolT;
    cudaGetSymbolAddress((void**)&WvhT, g_WvhT);
    cudaGetSymbolAddress((void**)&WvlT, g_WvlT);
    cudaGetSymbolAddress((void**)&WohT, g_WohT);
    cudaGetSymbolAddress((void**)&WolT, g_WolT);

    cudaFuncSetAttribute(fused_attn_kernel,
                         cudaFuncAttributeMaxDynamicSharedMemorySize, SMEM_FUSED);
    cudaFuncSetAttribute(hmma_sgemm,
                         cudaFuncAttributeMaxDynamicSharedMemorySize, SMEM_HMMA);

    compute_L_kernel<<<H_, 256>>>(W_A, W_A2);
    xy_kernel<<<B_*S_, 512>>>(q);
    split_wt_kernel<<<dim3(32, 32), 256>>>(Wv, WvhT, WvlT);
    split_wt_kernel<<<dim3(32, 32), 256>>>(Wo, WohT, WolT);
    hmma_sgemm<<<dim3(D_/128, M_ROWS/128), 256, SMEM_HMMA>>>(v, WvhT, WvlT, bv, vp);
    fused_attn_kernel<<<dim3(S_/128, BH_), 256, SMEM_FUSED>>>();
    hmma_sgemm<<<dim3(D_/128, M_ROWS/128), 256, SMEM_HMMA>>>(concat, WohT, WolT, bo, out);
}